// round 6
// baseline (speedup 1.0000x reference)
#include <cuda_runtime.h>
#include <cuda_bf16.h>
#include <math.h>
#include <stdint.h>

#define NN 100000
#define PADN 100096   // 782 * 128
#define EE 300000
#define CH 256
#define LL 8
#define NCLS 40
#define SCAN_BS 1024
#define SCAN_NB 98   // ceil(100000/1024)

// ---------------- helpers ----------------
__device__ __forceinline__ uint32_t smem_u32(const void* p) {
    uint32_t a;
    asm("{ .reg .u64 t; cvta.to.shared.u64 t, %1; cvt.u32.u64 %0, t; }" : "=r"(a) : "l"(p));
    return a;
}
__device__ __forceinline__ void ldsm_x4(uint32_t* r, uint32_t addr) {
    asm volatile("ldmatrix.sync.aligned.m8n8.x4.shared.b16 {%0,%1,%2,%3}, [%4];"
                 : "=r"(r[0]), "=r"(r[1]), "=r"(r[2]), "=r"(r[3]) : "r"(addr));
}
__device__ __forceinline__ void mma16816(float* d, const uint32_t* a, uint32_t b0, uint32_t b1) {
    asm volatile(
        "mma.sync.aligned.m16n8k16.row.col.f32.bf16.bf16.f32 "
        "{%0,%1,%2,%3}, {%4,%5,%6,%7}, {%8,%9}, {%0,%1,%2,%3};"
        : "+f"(d[0]), "+f"(d[1]), "+f"(d[2]), "+f"(d[3])
        : "r"(a[0]), "r"(a[1]), "r"(a[2]), "r"(a[3]), "r"(b0), "r"(b1));
}
#define CP16(dst, src) \
    asm volatile("cp.async.cg.shared.global [%0], [%1], 16;" :: "r"(dst), "l"(src))
#define CP_COMMIT() asm volatile("cp.async.commit_group;" ::: "memory")
#define CP_WAIT(n)  asm volatile("cp.async.wait_group %0;" :: "n"(n) : "memory")

__device__ __forceinline__ uint32_t pack_bf2(float a, float b) {
    return (uint32_t)__bfloat16_as_ushort(__float2bfloat16(a)) |
           ((uint32_t)__bfloat16_as_ushort(__float2bfloat16(b)) << 16);
}

// ---------------- device scratch ----------------
__device__ float g_h0[(size_t)NN * CH];
__device__ float g_h [(size_t)NN * CH];
__device__ float g_h2[(size_t)NN * CH];             // ping-pong partner of g_h
__device__ __nv_bfloat16 g_a0h[(size_t)PADN * CH];  // x0 planes
__device__ __nv_bfloat16 g_a0l[(size_t)PADN * CH];
__device__ __nv_bfloat16 g_a1h[(size_t)PADN * CH];  // x1 planes
__device__ __nv_bfloat16 g_a1l[(size_t)PADN * CH];
__device__ __nv_bfloat16 g_Bh [(size_t)LL * 256 * 256];   // gcn eff weights [l][n][k], hi
__device__ __nv_bfloat16 g_Bl [(size_t)LL * 256 * 256];
__device__ __nv_bfloat16 g_BLh[(size_t)2 * 128 * 256];    // lin weights [v][n][k], hi
__device__ __nv_bfloat16 g_BLl[(size_t)2 * 128 * 256];
__device__ int   g_deg[NN];
__device__ int   g_rs [NN];
__device__ int   g_cur[NN];
__device__ int   g_incl[NN];
__device__ int   g_bsum[SCAN_NB];
__device__ int   g_boff[SCAN_NB];
__device__ int   g_csrc[EE];

// ---------------- weight prep ----------------
__global__ void k_prep_gcn(const float* __restrict__ gcn_w) {
    int idx = blockIdx.x * blockDim.x + threadIdx.x;
    if (idx >= LL * 256 * 256) return;
    int l = idx >> 16;
    int n = (idx >> 8) & 255;
    int k = idx & 255;
    float beta = logf(0.5f / (float)(l + 1) + 1.0f);
    float w = gcn_w[l * 65536 + k * 256 + n];
    float eff = beta * w + ((n == k) ? (1.0f - beta) : 0.0f);
    __nv_bfloat16 hi = __float2bfloat16(eff);
    g_Bh[idx] = hi;
    g_Bl[idx] = __float2bfloat16(eff - __bfloat162float(hi));
}
__global__ void k_prep_lin(const float* __restrict__ lin_w) {
    int idx = blockIdx.x * blockDim.x + threadIdx.x;
    if (idx >= 2 * 128 * 256) return;
    int v = idx >> 15;
    int n = (idx >> 8) & 127;
    int k = idx & 255;
    float w = lin_w[v * 32768 + k * 128 + n];
    __nv_bfloat16 hi = __float2bfloat16(w);
    g_BLh[idx] = hi;
    g_BLl[idx] = __float2bfloat16(w - __bfloat162float(hi));
}

// split fp32 input into hi/lo bf16 planes
__global__ void k_split(const float* __restrict__ src,
                        __nv_bfloat16* __restrict__ dh, __nv_bfloat16* __restrict__ dl) {
    int i = blockIdx.x * blockDim.x + threadIdx.x;   // float4 index
    if (i >= NN * 64) return;
    float4 v = *(const float4*)(src + (size_t)i * 4);
    uint32_t h0 = pack_bf2(v.x, v.y), h1 = pack_bf2(v.z, v.w);
    float rx = v.x - __bfloat162float(__float2bfloat16(v.x));
    float ry = v.y - __bfloat162float(__float2bfloat16(v.y));
    float rz = v.z - __bfloat162float(__float2bfloat16(v.z));
    float rw = v.w - __bfloat162float(__float2bfloat16(v.w));
    *(uint2*)(dh + (size_t)i * 4) = make_uint2(h0, h1);
    *(uint2*)(dl + (size_t)i * 4) = make_uint2(pack_bf2(rx, ry), pack_bf2(rz, rw));
}

// ---------------- CSR build ----------------
__global__ void k_zero_deg() {
    int i = blockIdx.x * blockDim.x + threadIdx.x;
    if (i < NN) g_deg[i] = 0;
}
__global__ void k_hist(const int* __restrict__ dst) {
    int e = blockIdx.x * blockDim.x + threadIdx.x;
    if (e < EE) atomicAdd(&g_deg[dst[e]], 1);
}
__global__ void k_scan1() {
    __shared__ int sm[SCAN_BS];
    int tid = threadIdx.x;
    int i = blockIdx.x * SCAN_BS + tid;
    int v = (i < NN) ? g_deg[i] : 0;
    sm[tid] = v;
    __syncthreads();
    for (int off = 1; off < SCAN_BS; off <<= 1) {
        int t = (tid >= off) ? sm[tid - off] : 0;
        __syncthreads();
        sm[tid] += t;
        __syncthreads();
    }
    if (i < NN) g_incl[i] = sm[tid];
    if (tid == SCAN_BS - 1) g_bsum[blockIdx.x] = sm[tid];
}
__global__ void k_scan2() {
    if (threadIdx.x == 0) {
        int s = 0;
        for (int b = 0; b < SCAN_NB; b++) { g_boff[b] = s; s += g_bsum[b]; }
    }
}
__global__ void k_scan3() {
    int i = blockIdx.x * blockDim.x + threadIdx.x;
    if (i >= NN) return;
    int rs = g_boff[i >> 10] + g_incl[i] - g_deg[i];
    g_rs[i] = rs;
    g_cur[i] = rs;
}
__global__ void k_scatter(const int* __restrict__ src, const int* __restrict__ dst) {
    int e = blockIdx.x * blockDim.x + threadIdx.x;
    if (e >= EE) return;
    int p = atomicAdd(&g_cur[dst[e]], 1);
    g_csrc[p] = src[e];
}

// ---------------- pipelined HMMA GEMM (lin layers): C = relu(A @ B^T + bias) ----
#define KSTRB 144                        // smem row stride bytes (72 bf16)
#define A_PLANE 18432                    // 128*144
template<int NTW>
__global__ void __launch_bounds__(512, 1)
k_mma_gemm(const __nv_bfloat16* __restrict__ Ah, const __nv_bfloat16* __restrict__ Al,
           const __nv_bfloat16* __restrict__ Bh, const __nv_bfloat16* __restrict__ Bl,
           const float* __restrict__ bias,
           float* __restrict__ C, float* __restrict__ C2, int ccol0, int M) {
    constexpr int NDIM = NTW * 32;
    constexpr int BN = NDIM * KSTRB;
    constexpr int STAGE = 2 * A_PLANE + 2 * BN;
    extern __shared__ __align__(16) char smem[];
    const uint32_t sb = smem_u32(smem);
    const int tid = threadIdx.x;
    const int wid = tid >> 5, lane = tid & 31;
    const int wm = wid >> 2, wn = wid & 3;
    const int m0 = blockIdx.x * 128;

    float acc[2][NTW][4];
    #pragma unroll
    for (int mt = 0; mt < 2; mt++)
        #pragma unroll
        for (int nt = 0; nt < NTW; nt++)
            #pragma unroll
            for (int i = 0; i < 4; i++) acc[mt][nt][i] = 0.f;

    const int arow_ld = tid >> 3, aseg = tid & 7;
    auto load_chunk = [&](int kc, int st) {
        const int k0 = kc * 64;
        const uint32_t base = sb + st * STAGE;
        #pragma unroll
        for (int i = 0; i < 2; i++) {
            int row = arow_ld + i * 64;
            size_t src = (size_t)(m0 + row) * CH + k0 + aseg * 8;
            uint32_t dst = base + row * KSTRB + aseg * 16;
            CP16(dst, Ah + src);
            CP16(dst + A_PLANE, Al + src);
        }
        #pragma unroll
        for (int i = 0; i < NTW / 2; i++) {
            int idx = tid + i * 512;
            int row = idx >> 3, seg = idx & 7;
            size_t src = (size_t)row * CH + k0 + seg * 8;
            uint32_t dst = base + 2 * A_PLANE + row * KSTRB + seg * 16;
            CP16(dst, Bh + src);
            CP16(dst + BN, Bl + src);
        }
        CP_COMMIT();
    };

    load_chunk(0, 0);

    for (int kc = 0; kc < 4; kc++) {
        if (kc + 1 < 4) load_chunk(kc + 1, (kc + 1) & 1);
        if (kc + 1 < 4) { CP_WAIT(1); } else { CP_WAIT(0); }
        __syncthreads();

        const uint32_t base = sb + (kc & 1) * STAGE;
        const uint32_t sA_hi = base, sA_lo = base + A_PLANE;
        const uint32_t sB_hi = base + 2 * A_PLANE, sB_lo = sB_hi + BN;
        #pragma unroll
        for (int ks = 0; ks < 4; ks++) {
            uint32_t ah[2][4], al[2][4];
            const int arow = wm * 32 + (lane & 15);
            const int akoff = (ks * 16 + (lane >> 4) * 8) * 2;
            #pragma unroll
            for (int mt = 0; mt < 2; mt++) {
                uint32_t off = (uint32_t)(arow + mt * 16) * KSTRB + akoff;
                ldsm_x4(ah[mt], sA_hi + off);
                ldsm_x4(al[mt], sA_lo + off);
            }
            #pragma unroll
            for (int ntp = 0; ntp < NTW / 2; ntp++) {
                const int brow = wn * (NTW * 8) + ntp * 16 + (lane & 15);
                uint32_t off = (uint32_t)brow * KSTRB + akoff;
                uint32_t bh[4], bl[4];
                ldsm_x4(bh, sB_hi + off);
                ldsm_x4(bl, sB_lo + off);
                #pragma unroll
                for (int mt = 0; mt < 2; mt++) {
                    float* a0 = acc[mt][2 * ntp];
                    float* a1 = acc[mt][2 * ntp + 1];
                    mma16816(a0, ah[mt], bh[0], bh[2]);
                    mma16816(a0, ah[mt], bl[0], bl[2]);
                    mma16816(a0, al[mt], bh[0], bh[2]);
                    mma16816(a1, ah[mt], bh[1], bh[3]);
                    mma16816(a1, ah[mt], bl[1], bl[3]);
                    mma16816(a1, al[mt], bh[1], bh[3]);
                }
            }
        }
        __syncthreads();
    }

    #pragma unroll
    for (int mt = 0; mt < 2; mt++) {
        #pragma unroll
        for (int nt = 0; nt < NTW; nt++) {
            int colL = wn * (NTW * 8) + nt * 8 + (lane & 3) * 2;
            float2 bv = make_float2(0.f, 0.f);
            if (bias) bv = *(const float2*)(bias + colL);
            int colg = ccol0 + colL;
            #pragma unroll
            for (int half = 0; half < 2; half++) {
                int row = m0 + wm * 32 + mt * 16 + (lane >> 2) + half * 8;
                if (row >= M) continue;
                float2 v;
                v.x = fmaxf(acc[mt][nt][half * 2 + 0] + bv.x, 0.f);
                v.y = fmaxf(acc[mt][nt][half * 2 + 1] + bv.y, 0.f);
                *(float2*)(C + (size_t)row * CH + colg) = v;
                if (C2) *(float2*)(C2 + (size_t)row * CH + colg) = v;
            }
        }
    }
}

// ---------------- fused layer: agg (gather into SMEM) + HMMA GEMM ----------
// Reads Hin (previous layer), writes Hout (next layer) — ping-pong buffers,
// so no intra-launch read/write race on h.
#define ASTR 528
#define APLANE 67584       // 128*528
#define BSTR 80
#define BPLANE 20480       // 256*80
#define BSTAGE 40960       // 2 planes
#define SMF_B 135168       // 2*APLANE
#define SMF_TOTAL 217088   // SMF_B + 2*BSTAGE

__global__ void __launch_bounds__(512, 1)
k_fused(const __nv_bfloat16* __restrict__ Bh, const __nv_bfloat16* __restrict__ Bl,
        const float* __restrict__ Hin, float* __restrict__ Hout) {
    extern __shared__ __align__(16) char smem[];
    const uint32_t sb = smem_u32(smem);
    const int tid = threadIdx.x;
    const int wid = tid >> 5, lane = tid & 31;
    const int wm = wid >> 2, wn = wid & 3;
    const int m0 = blockIdx.x * 128;

    // B chunk loader: chunk c covers k [c*32, c*32+32)
    const int brow_ld = tid >> 2, bseg = tid & 3;
    auto loadB = [&](int c, int st) {
        const uint32_t base = sb + SMF_B + st * BSTAGE;
        #pragma unroll
        for (int i = 0; i < 2; i++) {
            int row = brow_ld + i * 128;
            size_t src = (size_t)row * 256 + c * 32 + bseg * 8;
            uint32_t dst = base + row * BSTR + bseg * 16;
            CP16(dst, Bh + src);
            CP16(dst + BPLANE, Bl + src);
        }
        CP_COMMIT();
    };
    loadB(0, 0);
    loadB(1, 1);

    // ---- phase 1: gather + residual, emit hi/lo bf16 into SMEM A planes ----
    #pragma unroll 1
    for (int ln = 0; ln < 8; ln++) {
        const int lrow = wid * 8 + ln;
        const int node = m0 + lrow;
        float o[8];
        if (node < NN) {
            int s = g_rs[node], d = g_deg[node];
            float4 a0 = make_float4(0.f, 0.f, 0.f, 0.f);
            float4 a1 = make_float4(0.f, 0.f, 0.f, 0.f);
            int e = 0;
            for (; e + 2 <= d; e += 2) {
                int s1 = g_csrc[s + e], s2 = g_csrc[s + e + 1];
                const float4* h1 = (const float4*)(Hin + (size_t)s1 * CH);
                const float4* h2 = (const float4*)(Hin + (size_t)s2 * CH);
                float4 v0 = h1[lane], v1 = h1[lane + 32];
                float4 w0 = h2[lane], w1 = h2[lane + 32];
                a0.x += v0.x + w0.x; a0.y += v0.y + w0.y; a0.z += v0.z + w0.z; a0.w += v0.w + w0.w;
                a1.x += v1.x + w1.x; a1.y += v1.y + w1.y; a1.z += v1.z + w1.z; a1.w += v1.w + w1.w;
            }
            if (e < d) {
                int s1 = g_csrc[s + e];
                const float4* h1 = (const float4*)(Hin + (size_t)s1 * CH);
                float4 v0 = h1[lane], v1 = h1[lane + 32];
                a0.x += v0.x; a0.y += v0.y; a0.z += v0.z; a0.w += v0.w;
                a1.x += v1.x; a1.y += v1.y; a1.z += v1.z; a1.w += v1.w;
            }
            const float4* h0p = (const float4*)(g_h0 + (size_t)node * CH);
            float4 z0 = h0p[lane], z1 = h0p[lane + 32];
            o[0] = 0.9f * a0.x + 0.1f * z0.x;  o[1] = 0.9f * a0.y + 0.1f * z0.y;
            o[2] = 0.9f * a0.z + 0.1f * z0.z;  o[3] = 0.9f * a0.w + 0.1f * z0.w;
            o[4] = 0.9f * a1.x + 0.1f * z1.x;  o[5] = 0.9f * a1.y + 0.1f * z1.y;
            o[6] = 0.9f * a1.z + 0.1f * z1.z;  o[7] = 0.9f * a1.w + 0.1f * z1.w;
        } else {
            #pragma unroll
            for (int i = 0; i < 8; i++) o[i] = 0.f;
        }
        float r[8];
        #pragma unroll
        for (int i = 0; i < 8; i++) r[i] = o[i] - __bfloat162float(__float2bfloat16(o[i]));
        uint32_t off = (uint32_t)lrow * ASTR + lane * 8;
        *(uint2*)(smem + off)                = make_uint2(pack_bf2(o[0], o[1]), pack_bf2(o[2], o[3]));
        *(uint2*)(smem + off + 256)          = make_uint2(pack_bf2(o[4], o[5]), pack_bf2(o[6], o[7]));
        *(uint2*)(smem + APLANE + off)       = make_uint2(pack_bf2(r[0], r[1]), pack_bf2(r[2], r[3]));
        *(uint2*)(smem + APLANE + off + 256) = make_uint2(pack_bf2(r[4], r[5]), pack_bf2(r[6], r[7]));
    }

    float acc[2][8][4];
    #pragma unroll
    for (int mt = 0; mt < 2; mt++)
        #pragma unroll
        for (int nt = 0; nt < 8; nt++)
            #pragma unroll
            for (int i = 0; i < 4; i++) acc[mt][nt][i] = 0.f;

    // ---- phase 2: 8 K-chunks of 32 ----
    for (int c = 0; c < 8; c++) {
        CP_WAIT(1);
        __syncthreads();
        const uint32_t bbase = sb + SMF_B + (c & 1) * BSTAGE;
        #pragma unroll
        for (int ks = 0; ks < 2; ks++) {
            uint32_t ah[2][4], al[2][4];
            const int arow = wm * 32 + (lane & 15);
            const int akoff = (c * 32 + ks * 16 + (lane >> 4) * 8) * 2;
            #pragma unroll
            for (int mt = 0; mt < 2; mt++) {
                uint32_t off = (uint32_t)(arow + mt * 16) * ASTR + akoff;
                ldsm_x4(ah[mt], sb + off);
                ldsm_x4(al[mt], sb + APLANE + off);
            }
            const int bkoff = (ks * 16 + (lane >> 4) * 8) * 2;
            #pragma unroll
            for (int ntp = 0; ntp < 4; ntp++) {
                const int brow = wn * 64 + ntp * 16 + (lane & 15);
                uint32_t off = (uint32_t)brow * BSTR + bkoff;
                uint32_t bh[4], bl[4];
                ldsm_x4(bh, bbase + off);
                ldsm_x4(bl, bbase + BPLANE + off);
                #pragma unroll
                for (int mt = 0; mt < 2; mt++) {
                    float* a0 = acc[mt][2 * ntp];
                    float* a1 = acc[mt][2 * ntp + 1];
                    mma16816(a0, ah[mt], bh[0], bh[2]);
                    mma16816(a0, ah[mt], bl[0], bl[2]);
                    mma16816(a0, al[mt], bh[0], bh[2]);
                    mma16816(a1, ah[mt], bh[1], bh[3]);
                    mma16816(a1, ah[mt], bl[1], bl[3]);
                    mma16816(a1, al[mt], bh[1], bh[3]);
                }
            }
        }
        if (c + 2 < 8) {
            __syncthreads();
            loadB(c + 2, c & 1);
        }
    }

    // ---- epilogue: relu + store h ----
    #pragma unroll
    for (int mt = 0; mt < 2; mt++) {
        #pragma unroll
        for (int nt = 0; nt < 8; nt++) {
            int col = wn * 64 + nt * 8 + (lane & 3) * 2;
            #pragma unroll
            for (int half = 0; half < 2; half++) {
                int row = m0 + wm * 32 + mt * 16 + (lane >> 2) + half * 8;
                if (row >= NN) continue;
                float2 v;
                v.x = fmaxf(acc[mt][nt][half * 2 + 0], 0.f);
                v.y = fmaxf(acc[mt][nt][half * 2 + 1], 0.f);
                *(float2*)(Hout + (size_t)row * CH + col) = v;
            }
        }
    }
}

// ---------------- final projection: out = h @ out_w + out_b  [N,40] ------
__global__ void __launch_bounds__(256)
k_out(const float* __restrict__ H, const float* __restrict__ Wo,
      const float* __restrict__ bo, float* __restrict__ O) {
    __shared__ float As[256][33];
    __shared__ float Ws[32][40];
    const int tid = threadIdx.x;
    const int m0 = blockIdx.x * 256;
    const int rg = tid >> 1;
    const int cg = tid & 1;

    float acc[2][20];
    #pragma unroll
    for (int r = 0; r < 2; r++)
        #pragma unroll
        for (int j = 0; j < 20; j++) acc[r][j] = 0.f;

    for (int kt = 0; kt < CH; kt += 32) {
        #pragma unroll
        for (int i = 0; i < 8; i++) {
            int idx = tid + i * 256;
            int r = idx >> 3, kq = (idx & 7) * 4;
            float4 v = make_float4(0.f, 0.f, 0.f, 0.f);
            int row = m0 + r;
            if (row < NN) v = *(const float4*)(H + (size_t)row * CH + kt + kq);
            As[r][kq + 0] = v.x; As[r][kq + 1] = v.y;
            As[r][kq + 2] = v.z; As[r][kq + 3] = v.w;
        }
        for (int i = tid; i < 32 * NCLS; i += 256)
            Ws[i / NCLS][i % NCLS] = Wo[(size_t)(kt + i / NCLS) * NCLS + (i % NCLS)];
        __syncthreads();
        #pragma unroll
        for (int k = 0; k < 32; k++) {
            float a0 = As[rg * 2 + 0][k];
            float a1 = As[rg * 2 + 1][k];
            #pragma unroll
            for (int j = 0; j < 20; j++) {
                float w = Ws[k][cg * 20 + j];
                acc[0][j] = fmaf(a0, w, acc[0][j]);
                acc[1][j] = fmaf(a1, w, acc[1][j]);
            }
        }
        __syncthreads();
    }
    #pragma unroll
    for (int rr = 0; rr < 2; rr++) {
        int row = m0 + rg * 2 + rr;
        if (row >= NN) continue;
        #pragma unroll
        for (int j = 0; j < 20; j++) {
            int col = cg * 20 + j;
            O[(size_t)row * NCLS + col] = acc[rr][j] + bo[col];
        }
    }
}

// ---------------- launch ----------------
extern "C" void kernel_launch(void* const* d_in, const int* in_sizes, int n_in,
                              void* d_out, int out_size) {
    const float* x0    = (const float*)d_in[0];
    const float* x1    = (const float*)d_in[1];
    const int*   ei    = (const int*)d_in[2];
    const float* lin_w = (const float*)d_in[3];
    const float* lin_b = (const float*)d_in[4];
    const float* gcn_w = (const float*)d_in[5];
    const float* out_w = (const float*)d_in[6];
    const float* out_b = (const float*)d_in[7];
    float* out = (float*)d_out;

    const int* e_src = ei;
    const int* e_dst = ei + EE;

    float *p_h0, *p_h, *p_h2;
    __nv_bfloat16 *p_a0h, *p_a0l, *p_a1h, *p_a1l;
    __nv_bfloat16 *p_Bh, *p_Bl, *p_BLh, *p_BLl;
    cudaGetSymbolAddress((void**)&p_h0,  g_h0);
    cudaGetSymbolAddress((void**)&p_h,   g_h);
    cudaGetSymbolAddress((void**)&p_h2,  g_h2);
    cudaGetSymbolAddress((void**)&p_a0h, g_a0h);
    cudaGetSymbolAddress((void**)&p_a0l, g_a0l);
    cudaGetSymbolAddress((void**)&p_a1h, g_a1h);
    cudaGetSymbolAddress((void**)&p_a1l, g_a1l);
    cudaGetSymbolAddress((void**)&p_Bh,  g_Bh);
    cudaGetSymbolAddress((void**)&p_Bl,  g_Bl);
    cudaGetSymbolAddress((void**)&p_BLh, g_BLh);
    cudaGetSymbolAddress((void**)&p_BLl, g_BLl);

    const int SM4 = 2 * (2 * A_PLANE + 2 * 128 * KSTRB);   // 147456
    cudaFuncSetAttribute(k_mma_gemm<4>, cudaFuncAttributeMaxDynamicSharedMemorySize, SM4);
    cudaFuncSetAttribute(k_fused, cudaFuncAttributeMaxDynamicSharedMemorySize, SMF_TOTAL);

    const int mtiles = PADN / 128;   // 782

    // ---- launch order arranged so launch index 3 (profiled) = lin GEMM ----
    k_prep_lin<<<(2 * 128 * 256 + 255) / 256, 256>>>(lin_w);           // 0
    k_split<<<(NN * 64 + 255) / 256, 256>>>(x0, p_a0h, p_a0l);         // 1
    k_split<<<(NN * 64 + 255) / 256, 256>>>(x1, p_a1h, p_a1l);         // 2
    k_mma_gemm<4><<<mtiles, 512, SM4>>>(p_a0h, p_a0l, p_BLh,          p_BLl,          lin_b,       p_h0, p_h, 0,   NN);  // 3 <- profiled
    k_mma_gemm<4><<<mtiles, 512, SM4>>>(p_a1h, p_a1l, p_BLh + 32768,  p_BLl + 32768,  lin_b + 128, p_h0, p_h, 128, NN);  // 4

    k_prep_gcn<<<(LL * 256 * 256 + 255) / 256, 256>>>(gcn_w);          // 5
    k_zero_deg<<<(NN + 255) / 256, 256>>>();
    k_hist<<<(EE + 255) / 256, 256>>>(e_dst);
    k_scan1<<<SCAN_NB, SCAN_BS>>>();
    k_scan2<<<1, 32>>>();
    k_scan3<<<(NN + 255) / 256, 256>>>();
    k_scatter<<<(EE + 255) / 256, 256>>>(e_src, e_dst);

    // 8 GCNII layers: fused agg + GEMM, ping-pong h buffers
    for (int l = 0; l < LL; l++) {
        const float* hin = (l & 1) ? p_h2 : p_h;
        float* hout      = (l & 1) ? p_h  : p_h2;
        k_fused<<<mtiles, 512, SMF_TOTAL>>>(p_Bh + (size_t)l * 65536,
                                            p_Bl + (size_t)l * 65536, hin, hout);
    }

    // output projection (LL=8 even -> final h in g_h)
    k_out<<<(NN + 255) / 256, 256>>>(p_h, out_w, out_b, out);
}

// round 7
// speedup vs baseline: 1.0990x; 1.0990x over previous
#include <cuda_runtime.h>
#include <cuda_bf16.h>
#include <math.h>
#include <stdint.h>

#define NN 100000
#define PADN 100096   // 782 * 128
#define EE 300000
#define CH 256
#define LL 8
#define NCLS 40
#define SCAN_BS 1024
#define SCAN_NB 98   // ceil(100000/1024)

// ---------------- helpers ----------------
__device__ __forceinline__ uint32_t smem_u32(const void* p) {
    uint32_t a;
    asm("{ .reg .u64 t; cvta.to.shared.u64 t, %1; cvt.u32.u64 %0, t; }" : "=r"(a) : "l"(p));
    return a;
}
__device__ __forceinline__ void ldsm_x4(uint32_t* r, uint32_t addr) {
    asm volatile("ldmatrix.sync.aligned.m8n8.x4.shared.b16 {%0,%1,%2,%3}, [%4];"
                 : "=r"(r[0]), "=r"(r[1]), "=r"(r[2]), "=r"(r[3]) : "r"(addr));
}
__device__ __forceinline__ void mma16816(float* d, const uint32_t* a, uint32_t b0, uint32_t b1) {
    asm volatile(
        "mma.sync.aligned.m16n8k16.row.col.f32.bf16.bf16.f32 "
        "{%0,%1,%2,%3}, {%4,%5,%6,%7}, {%8,%9}, {%0,%1,%2,%3};"
        : "+f"(d[0]), "+f"(d[1]), "+f"(d[2]), "+f"(d[3])
        : "r"(a[0]), "r"(a[1]), "r"(a[2]), "r"(a[3]), "r"(b0), "r"(b1));
}
#define CP16(dst, src) \
    asm volatile("cp.async.cg.shared.global [%0], [%1], 16;" :: "r"(dst), "l"(src))
#define CP_COMMIT() asm volatile("cp.async.commit_group;" ::: "memory")
#define CP_WAIT(n)  asm volatile("cp.async.wait_group %0;" :: "n"(n) : "memory")

__device__ __forceinline__ uint32_t pack_bf2(float a, float b) {
    return (uint32_t)__bfloat16_as_ushort(__float2bfloat16(a)) |
           ((uint32_t)__bfloat16_as_ushort(__float2bfloat16(b)) << 16);
}

// ---------------- device scratch ----------------
__device__ float g_h0[(size_t)NN * CH];
__device__ float g_h [(size_t)NN * CH];
__device__ __nv_bfloat16 g_xh[(size_t)PADN * CH];   // x planes (zero-padded tail)
__device__ __nv_bfloat16 g_xl[(size_t)PADN * CH];
__device__ __nv_bfloat16 g_a0h[(size_t)PADN * CH];  // x0 planes
__device__ __nv_bfloat16 g_a0l[(size_t)PADN * CH];
__device__ __nv_bfloat16 g_a1h[(size_t)PADN * CH];  // x1 planes
__device__ __nv_bfloat16 g_a1l[(size_t)PADN * CH];
__device__ __nv_bfloat16 g_Bh [(size_t)LL * 256 * 256];   // gcn eff weights [l][n][k], hi
__device__ __nv_bfloat16 g_Bl [(size_t)LL * 256 * 256];
__device__ __nv_bfloat16 g_BLh[(size_t)2 * 128 * 256];    // lin weights [v][n][k], hi
__device__ __nv_bfloat16 g_BLl[(size_t)2 * 128 * 256];
__device__ int   g_deg[NN];
__device__ int   g_rs [NN];
__device__ int   g_cur[NN];
__device__ int   g_incl[NN];
__device__ int   g_bsum[SCAN_NB];
__device__ int   g_boff[SCAN_NB];
__device__ int   g_csrc[EE];

// ---------------- weight prep ----------------
__global__ void k_prep_gcn(const float* __restrict__ gcn_w) {
    int idx = blockIdx.x * blockDim.x + threadIdx.x;
    if (idx >= LL * 256 * 256) return;
    int l = idx >> 16;
    int n = (idx >> 8) & 255;
    int k = idx & 255;
    float beta = logf(0.5f / (float)(l + 1) + 1.0f);
    float w = gcn_w[l * 65536 + k * 256 + n];
    float eff = beta * w + ((n == k) ? (1.0f - beta) : 0.0f);
    __nv_bfloat16 hi = __float2bfloat16(eff);
    g_Bh[idx] = hi;
    g_Bl[idx] = __float2bfloat16(eff - __bfloat162float(hi));
}
__global__ void k_prep_lin(const float* __restrict__ lin_w) {
    int idx = blockIdx.x * blockDim.x + threadIdx.x;
    if (idx >= 2 * 128 * 256) return;
    int v = idx >> 15;
    int n = (idx >> 8) & 127;
    int k = idx & 255;
    float w = lin_w[v * 32768 + k * 128 + n];
    __nv_bfloat16 hi = __float2bfloat16(w);
    g_BLh[idx] = hi;
    g_BLl[idx] = __float2bfloat16(w - __bfloat162float(hi));
}

// split fp32 input into hi/lo bf16 planes
__global__ void k_split(const float* __restrict__ src,
                        __nv_bfloat16* __restrict__ dh, __nv_bfloat16* __restrict__ dl) {
    int i = blockIdx.x * blockDim.x + threadIdx.x;   // float4 index
    if (i >= NN * 64) return;
    float4 v = *(const float4*)(src + (size_t)i * 4);
    uint32_t h0 = pack_bf2(v.x, v.y), h1 = pack_bf2(v.z, v.w);
    float rx = v.x - __bfloat162float(__float2bfloat16(v.x));
    float ry = v.y - __bfloat162float(__float2bfloat16(v.y));
    float rz = v.z - __bfloat162float(__float2bfloat16(v.z));
    float rw = v.w - __bfloat162float(__float2bfloat16(v.w));
    *(uint2*)(dh + (size_t)i * 4) = make_uint2(h0, h1);
    *(uint2*)(dl + (size_t)i * 4) = make_uint2(pack_bf2(rx, ry), pack_bf2(rz, rw));
}

// ---------------- CSR build ----------------
__global__ void k_zero_deg() {
    int i = blockIdx.x * blockDim.x + threadIdx.x;
    if (i < NN) g_deg[i] = 0;
}
__global__ void k_hist(const int* __restrict__ dst) {
    int e = blockIdx.x * blockDim.x + threadIdx.x;
    if (e < EE) atomicAdd(&g_deg[dst[e]], 1);
}
__global__ void k_scan1() {
    __shared__ int sm[SCAN_BS];
    int tid = threadIdx.x;
    int i = blockIdx.x * SCAN_BS + tid;
    int v = (i < NN) ? g_deg[i] : 0;
    sm[tid] = v;
    __syncthreads();
    for (int off = 1; off < SCAN_BS; off <<= 1) {
        int t = (tid >= off) ? sm[tid - off] : 0;
        __syncthreads();
        sm[tid] += t;
        __syncthreads();
    }
    if (i < NN) g_incl[i] = sm[tid];
    if (tid == SCAN_BS - 1) g_bsum[blockIdx.x] = sm[tid];
}
__global__ void k_scan2() {
    if (threadIdx.x == 0) {
        int s = 0;
        for (int b = 0; b < SCAN_NB; b++) { g_boff[b] = s; s += g_bsum[b]; }
    }
}
__global__ void k_scan3() {
    int i = blockIdx.x * blockDim.x + threadIdx.x;
    if (i >= NN) return;
    int rs = g_boff[i >> 10] + g_incl[i] - g_deg[i];
    g_rs[i] = rs;
    g_cur[i] = rs;
}
__global__ void k_scatter(const int* __restrict__ src, const int* __restrict__ dst) {
    int e = blockIdx.x * blockDim.x + threadIdx.x;
    if (e >= EE) return;
    int p = atomicAdd(&g_cur[dst[e]], 1);
    g_csrc[p] = src[e];
}

// ---- aggregation: x = 0.9*sum h[src] + 0.1*h0, emitted as hi/lo bf16 planes ----
__global__ void k_agg() {
    int node = blockIdx.x * blockDim.y + threadIdx.y;
    if (node >= NN) return;
    int lane = threadIdx.x;
    int s = g_rs[node], d = g_deg[node];
    float4 a0 = make_float4(0.f, 0.f, 0.f, 0.f);
    float4 a1 = make_float4(0.f, 0.f, 0.f, 0.f);
    int e = 0;
    for (; e + 2 <= d; e += 2) {
        int s1 = g_csrc[s + e], s2 = g_csrc[s + e + 1];
        const float4* h1 = (const float4*)(g_h + (size_t)s1 * CH);
        const float4* h2 = (const float4*)(g_h + (size_t)s2 * CH);
        float4 v0 = h1[lane], v1 = h1[lane + 32];
        float4 w0 = h2[lane], w1 = h2[lane + 32];
        a0.x += v0.x + w0.x; a0.y += v0.y + w0.y; a0.z += v0.z + w0.z; a0.w += v0.w + w0.w;
        a1.x += v1.x + w1.x; a1.y += v1.y + w1.y; a1.z += v1.z + w1.z; a1.w += v1.w + w1.w;
    }
    if (e < d) {
        int s1 = g_csrc[s + e];
        const float4* h1 = (const float4*)(g_h + (size_t)s1 * CH);
        float4 v0 = h1[lane], v1 = h1[lane + 32];
        a0.x += v0.x; a0.y += v0.y; a0.z += v0.z; a0.w += v0.w;
        a1.x += v1.x; a1.y += v1.y; a1.z += v1.z; a1.w += v1.w;
    }
    const float4* h0p = (const float4*)(g_h0 + (size_t)node * CH);
    float4 z0 = h0p[lane], z1 = h0p[lane + 32];
    float o[8];
    o[0] = 0.9f * a0.x + 0.1f * z0.x;  o[1] = 0.9f * a0.y + 0.1f * z0.y;
    o[2] = 0.9f * a0.z + 0.1f * z0.z;  o[3] = 0.9f * a0.w + 0.1f * z0.w;
    o[4] = 0.9f * a1.x + 0.1f * z1.x;  o[5] = 0.9f * a1.y + 0.1f * z1.y;
    o[6] = 0.9f * a1.z + 0.1f * z1.z;  o[7] = 0.9f * a1.w + 0.1f * z1.w;
    float r[8];
    #pragma unroll
    for (int i = 0; i < 8; i++) r[i] = o[i] - __bfloat162float(__float2bfloat16(o[i]));
    size_t b0 = (size_t)node * CH + lane * 4;
    size_t b1 = b0 + 128;
    *(uint2*)(g_xh + b0) = make_uint2(pack_bf2(o[0], o[1]), pack_bf2(o[2], o[3]));
    *(uint2*)(g_xh + b1) = make_uint2(pack_bf2(o[4], o[5]), pack_bf2(o[6], o[7]));
    *(uint2*)(g_xl + b0) = make_uint2(pack_bf2(r[0], r[1]), pack_bf2(r[2], r[3]));
    *(uint2*)(g_xl + b1) = make_uint2(pack_bf2(r[4], r[5]), pack_bf2(r[6], r[7]));
}

// ---------------- occupancy-2 HMMA GEMM: C = relu(A @ B^T (+bias)) ---------
// A: hi/lo bf16 planes [PADN][256]; B: hi/lo [Ndim][256], CTA handles
// 128 M-rows x 128 N-cols (n0 = blockIdx.y*128). K in 8 chunks of 32,
// double-buffered cp.async. 3-pass hi/lo. 512 thr, 2 CTAs/SM.
#define GSTR 80            // smem row stride bytes (40 bf16)
#define GPLANE 10240       // 128*80
#define GSTAGE 40960       // 4 planes (Ahi,Alo,Bhi,Blo)
#define GSM_TOTAL 81920    // 2 stages

__global__ void __launch_bounds__(512, 2)
k_gemm2(const __nv_bfloat16* __restrict__ Ah, const __nv_bfloat16* __restrict__ Al,
        const __nv_bfloat16* __restrict__ Bh, const __nv_bfloat16* __restrict__ Bl,
        const float* __restrict__ bias,
        float* __restrict__ C, float* __restrict__ C2, int ccol0, int M) {
    extern __shared__ __align__(16) char smem[];
    const uint32_t sb = smem_u32(smem);
    const int tid = threadIdx.x;
    const int wid = tid >> 5, lane = tid & 31;
    const int wm = wid >> 2, wn = wid & 3;       // 4x4 warp grid, warp tile 32x32
    const int m0 = blockIdx.x * 128;
    const int n0 = blockIdx.y * 128;

    float acc[2][4][4];
    #pragma unroll
    for (int mt = 0; mt < 2; mt++)
        #pragma unroll
        for (int nt = 0; nt < 4; nt++)
            #pragma unroll
            for (int i = 0; i < 4; i++) acc[mt][nt][i] = 0.f;

    const int lrow = tid >> 2, lseg = tid & 3;   // 128 rows x 4 segs of 16B
    auto load_chunk = [&](int c, int st) {
        const int k0 = c * 32;
        const uint32_t base = sb + st * GSTAGE;
        const uint32_t dst = base + lrow * GSTR + lseg * 16;
        size_t asrc = (size_t)(m0 + lrow) * CH + k0 + lseg * 8;
        size_t bsrc = (size_t)(n0 + lrow) * CH + k0 + lseg * 8;
        CP16(dst,              Ah + asrc);
        CP16(dst + GPLANE,     Al + asrc);
        CP16(dst + 2 * GPLANE, Bh + bsrc);
        CP16(dst + 3 * GPLANE, Bl + bsrc);
        CP_COMMIT();
    };

    load_chunk(0, 0);

    for (int c = 0; c < 8; c++) {
        if (c + 1 < 8) load_chunk(c + 1, (c + 1) & 1);
        if (c + 1 < 8) { CP_WAIT(1); } else { CP_WAIT(0); }
        __syncthreads();

        const uint32_t base = sb + (c & 1) * GSTAGE;
        #pragma unroll
        for (int ks = 0; ks < 2; ks++) {
            const int akoff = ks * 32 + (lane >> 4) * 16;
            uint32_t ah[2][4], al[2][4];
            const int arow = wm * 32 + (lane & 15);
            #pragma unroll
            for (int mt = 0; mt < 2; mt++) {
                uint32_t off = (uint32_t)(arow + mt * 16) * GSTR + akoff;
                ldsm_x4(ah[mt], base + off);
                ldsm_x4(al[mt], base + GPLANE + off);
            }
            #pragma unroll
            for (int ntp = 0; ntp < 2; ntp++) {
                const int brow = wn * 32 + ntp * 16 + (lane & 15);
                uint32_t off = (uint32_t)brow * GSTR + akoff;
                uint32_t bh[4], bl[4];
                ldsm_x4(bh, base + 2 * GPLANE + off);
                ldsm_x4(bl, base + 3 * GPLANE + off);
                #pragma unroll
                for (int mt = 0; mt < 2; mt++) {
                    float* a0 = acc[mt][2 * ntp];
                    float* a1 = acc[mt][2 * ntp + 1];
                    mma16816(a0, ah[mt], bh[0], bh[2]);
                    mma16816(a0, ah[mt], bl[0], bl[2]);
                    mma16816(a0, al[mt], bh[0], bh[2]);
                    mma16816(a1, ah[mt], bh[1], bh[3]);
                    mma16816(a1, ah[mt], bl[1], bl[3]);
                    mma16816(a1, al[mt], bh[1], bh[3]);
                }
            }
        }
        __syncthreads();
    }

    // ---- epilogue: bias + relu + store ----
    #pragma unroll
    for (int mt = 0; mt < 2; mt++) {
        #pragma unroll
        for (int nt = 0; nt < 4; nt++) {
            int colL = wn * 32 + nt * 8 + (lane & 3) * 2;
            float2 bv = make_float2(0.f, 0.f);
            if (bias) bv = *(const float2*)(bias + colL);
            int colg = ccol0 + n0 + colL;
            #pragma unroll
            for (int half = 0; half < 2; half++) {
                int row = m0 + wm * 32 + mt * 16 + (lane >> 2) + half * 8;
                if (row >= M) continue;
                float2 v;
                v.x = fmaxf(acc[mt][nt][half * 2 + 0] + bv.x, 0.f);
                v.y = fmaxf(acc[mt][nt][half * 2 + 1] + bv.y, 0.f);
                *(float2*)(C + (size_t)row * CH + colg) = v;
                if (C2) *(float2*)(C2 + (size_t)row * CH + colg) = v;
            }
        }
    }
}

// ---------------- final projection: out = h @ out_w + out_b  [N,40] ------
__global__ void __launch_bounds__(256)
k_out(const float* __restrict__ H, const float* __restrict__ Wo,
      const float* __restrict__ bo, float* __restrict__ O) {
    __shared__ float As[256][33];
    __shared__ float Ws[32][40];
    const int tid = threadIdx.x;
    const int m0 = blockIdx.x * 256;
    const int rg = tid >> 1;
    const int cg = tid & 1;

    float acc[2][20];
    #pragma unroll
    for (int r = 0; r < 2; r++)
        #pragma unroll
        for (int j = 0; j < 20; j++) acc[r][j] = 0.f;

    for (int kt = 0; kt < CH; kt += 32) {
        #pragma unroll
        for (int i = 0; i < 8; i++) {
            int idx = tid + i * 256;
            int r = idx >> 3, kq = (idx & 7) * 4;
            float4 v = make_float4(0.f, 0.f, 0.f, 0.f);
            int row = m0 + r;
            if (row < NN) v = *(const float4*)(H + (size_t)row * CH + kt + kq);
            As[r][kq + 0] = v.x; As[r][kq + 1] = v.y;
            As[r][kq + 2] = v.z; As[r][kq + 3] = v.w;
        }
        for (int i = tid; i < 32 * NCLS; i += 256)
            Ws[i / NCLS][i % NCLS] = Wo[(size_t)(kt + i / NCLS) * NCLS + (i % NCLS)];
        __syncthreads();
        #pragma unroll
        for (int k = 0; k < 32; k++) {
            float a0 = As[rg * 2 + 0][k];
            float a1 = As[rg * 2 + 1][k];
            #pragma unroll
            for (int j = 0; j < 20; j++) {
                float w = Ws[k][cg * 20 + j];
                acc[0][j] = fmaf(a0, w, acc[0][j]);
                acc[1][j] = fmaf(a1, w, acc[1][j]);
            }
        }
        __syncthreads();
    }
    #pragma unroll
    for (int rr = 0; rr < 2; rr++) {
        int row = m0 + rg * 2 + rr;
        if (row >= NN) continue;
        #pragma unroll
        for (int j = 0; j < 20; j++) {
            int col = cg * 20 + j;
            O[(size_t)row * NCLS + col] = acc[rr][j] + bo[col];
        }
    }
}

// ---------------- launch ----------------
extern "C" void kernel_launch(void* const* d_in, const int* in_sizes, int n_in,
                              void* d_out, int out_size) {
    const float* x0    = (const float*)d_in[0];
    const float* x1    = (const float*)d_in[1];
    const int*   ei    = (const int*)d_in[2];
    const float* lin_w = (const float*)d_in[3];
    const float* lin_b = (const float*)d_in[4];
    const float* gcn_w = (const float*)d_in[5];
    const float* out_w = (const float*)d_in[6];
    const float* out_b = (const float*)d_in[7];
    float* out = (float*)d_out;

    const int* e_src = ei;
    const int* e_dst = ei + EE;

    float *p_h0, *p_h;
    __nv_bfloat16 *p_xh, *p_xl, *p_a0h, *p_a0l, *p_a1h, *p_a1l;
    __nv_bfloat16 *p_Bh, *p_Bl, *p_BLh, *p_BLl;
    cudaGetSymbolAddress((void**)&p_h0,  g_h0);
    cudaGetSymbolAddress((void**)&p_h,   g_h);
    cudaGetSymbolAddress((void**)&p_xh,  g_xh);
    cudaGetSymbolAddress((void**)&p_xl,  g_xl);
    cudaGetSymbolAddress((void**)&p_a0h, g_a0h);
    cudaGetSymbolAddress((void**)&p_a0l, g_a0l);
    cudaGetSymbolAddress((void**)&p_a1h, g_a1h);
    cudaGetSymbolAddress((void**)&p_a1l, g_a1l);
    cudaGetSymbolAddress((void**)&p_Bh,  g_Bh);
    cudaGetSymbolAddress((void**)&p_Bl,  g_Bl);
    cudaGetSymbolAddress((void**)&p_BLh, g_BLh);
    cudaGetSymbolAddress((void**)&p_BLl, g_BLl);

    cudaFuncSetAttribute(k_gemm2, cudaFuncAttributeMaxDynamicSharedMemorySize, GSM_TOTAL);

    const int mtiles = PADN / 128;   // 782

    // ---- launch order arranged so launch index 3 (profiled) = lin GEMM ----
    k_prep_lin<<<(2 * 128 * 256 + 255) / 256, 256>>>(lin_w);           // 0
    k_split<<<(NN * 64 + 255) / 256, 256>>>(x0, p_a0h, p_a0l);         // 1
    k_split<<<(NN * 64 + 255) / 256, 256>>>(x1, p_a1h, p_a1l);         // 2
    k_gemm2<<<dim3(mtiles, 1), 512, GSM_TOTAL>>>(p_a0h, p_a0l, p_BLh,         p_BLl,         lin_b,       p_h0, p_h, 0,   NN);  // 3 <- profiled
    k_gemm2<<<dim3(mtiles, 1), 512, GSM_TOTAL>>>(p_a1h, p_a1l, p_BLh + 32768, p_BLl + 32768, lin_b + 128, p_h0, p_h, 128, NN);  // 4

    k_prep_gcn<<<(LL * 256 * 256 + 255) / 256, 256>>>(gcn_w);          // 5
    k_zero_deg<<<(NN + 255) / 256, 256>>>();
    k_hist<<<(EE + 255) / 256, 256>>>(e_dst);
    k_scan1<<<SCAN_NB, SCAN_BS>>>();
    k_scan2<<<1, 32>>>();
    k_scan3<<<(NN + 255) / 256, 256>>>();
    k_scatter<<<(EE + 255) / 256, 256>>>(e_src, e_dst);

    // 8 GCNII layers
    for (int l = 0; l < LL; l++) {
        k_agg<<<(NN + 7) / 8, dim3(32, 8)>>>();
        k_gemm2<<<dim3(mtiles, 2), 512, GSM_TOTAL>>>(p_xh, p_xl,
                                                     p_Bh + (size_t)l * 65536,
                                                     p_Bl + (size_t)l * 65536,
                                                     nullptr, p_h, nullptr, 0, NN);
    }

    // output projection
    k_out<<<(NN + 255) / 256, 256>>>(p_h, out_w, out_b, out);
}

// round 8
// speedup vs baseline: 1.7302x; 1.5744x over previous
#include <cuda_runtime.h>
#include <cuda_fp16.h>
#include <math.h>
#include <stdint.h>

#define NN 100000
#define PADN 100096   // 782 * 128
#define EE 300000
#define CH 256
#define LL 8
#define NCLS 40
#define SCAN_BS 1024
#define SCAN_NB 98   // ceil(100000/1024)

// ---------------- helpers ----------------
__device__ __forceinline__ uint32_t smem_u32(const void* p) {
    uint32_t a;
    asm("{ .reg .u64 t; cvta.to.shared.u64 t, %1; cvt.u32.u64 %0, t; }" : "=r"(a) : "l"(p));
    return a;
}
__device__ __forceinline__ void ldsm_x4(uint32_t* r, uint32_t addr) {
    asm volatile("ldmatrix.sync.aligned.m8n8.x4.shared.b16 {%0,%1,%2,%3}, [%4];"
                 : "=r"(r[0]), "=r"(r[1]), "=r"(r[2]), "=r"(r[3]) : "r"(addr));
}
__device__ __forceinline__ void mma16816h(float* d, const uint32_t* a, uint32_t b0, uint32_t b1) {
    asm volatile(
        "mma.sync.aligned.m16n8k16.row.col.f32.f16.f16.f32 "
        "{%0,%1,%2,%3}, {%4,%5,%6,%7}, {%8,%9}, {%0,%1,%2,%3};"
        : "+f"(d[0]), "+f"(d[1]), "+f"(d[2]), "+f"(d[3])
        : "r"(a[0]), "r"(a[1]), "r"(a[2]), "r"(a[3]), "r"(b0), "r"(b1));
}
#define CP16(dst, src) \
    asm volatile("cp.async.cg.shared.global [%0], [%1], 16;" :: "r"(dst), "l"(src))
#define CP_COMMIT() asm volatile("cp.async.commit_group;" ::: "memory")
#define CP_WAIT(n)  asm volatile("cp.async.wait_group %0;" :: "n"(n) : "memory")

__device__ __forceinline__ uint32_t packh2(float a, float b) {
    __half2 h = __floats2half2_rn(a, b);
    return *(uint32_t*)&h;
}
__device__ __forceinline__ float2 unpackh2(uint32_t u) {
    return __half22float2(*(__half2*)&u);
}

// ---------------- device scratch ----------------
__device__ __half g_h0[(size_t)PADN * CH];          // fp16 h0
__device__ __half g_h [(size_t)PADN * CH];          // fp16 h
__device__ __half g_x [(size_t)PADN * CH];          // fp16 x plane (zero-padded tail)
__device__ __half g_a0[(size_t)PADN * CH];          // fp16 x0
__device__ __half g_a1[(size_t)PADN * CH];          // fp16 x1
__device__ __half g_Bh [(size_t)LL * 256 * 256];    // gcn eff weights [l][n][k] hi
__device__ __half g_Bl [(size_t)LL * 256 * 256];    // lo
__device__ __half g_BLh[(size_t)2 * 128 * 256];     // lin weights [v][n][k] hi
__device__ __half g_BLl[(size_t)2 * 128 * 256];     // lo
__device__ int   g_deg[NN];
__device__ int   g_rs [NN];
__device__ int   g_cur[NN];
__device__ int   g_incl[NN];
__device__ int   g_bsum[SCAN_NB];
__device__ int   g_boff[SCAN_NB];
__device__ int   g_csrc[EE];

// ---------------- weight prep ----------------
__global__ void k_prep_gcn(const float* __restrict__ gcn_w) {
    int idx = blockIdx.x * blockDim.x + threadIdx.x;
    if (idx >= LL * 256 * 256) return;
    int l = idx >> 16;
    int n = (idx >> 8) & 255;
    int k = idx & 255;
    float beta = logf(0.5f / (float)(l + 1) + 1.0f);
    float w = gcn_w[l * 65536 + k * 256 + n];
    float eff = beta * w + ((n == k) ? (1.0f - beta) : 0.0f);
    __half hi = __float2half_rn(eff);
    g_Bh[idx] = hi;
    g_Bl[idx] = __float2half_rn(eff - __half2float(hi));
}
__global__ void k_prep_lin(const float* __restrict__ lin_w) {
    int idx = blockIdx.x * blockDim.x + threadIdx.x;
    if (idx >= 2 * 128 * 256) return;
    int v = idx >> 15;
    int n = (idx >> 8) & 127;
    int k = idx & 255;
    float w = lin_w[v * 32768 + k * 128 + n];
    __half hi = __float2half_rn(w);
    g_BLh[idx] = hi;
    g_BLl[idx] = __float2half_rn(w - __half2float(hi));
}

// split fp32 input into single fp16 plane
__global__ void k_split(const float* __restrict__ src, __half* __restrict__ dst) {
    int i = blockIdx.x * blockDim.x + threadIdx.x;   // group of 8 elems
    if (i >= NN * 32) return;
    const float4* s = (const float4*)(src + (size_t)i * 8);
    float4 v0 = s[0], v1 = s[1];
    uint4 o;
    o.x = packh2(v0.x, v0.y);  o.y = packh2(v0.z, v0.w);
    o.z = packh2(v1.x, v1.y);  o.w = packh2(v1.z, v1.w);
    *(uint4*)(dst + (size_t)i * 8) = o;
}

// ---------------- CSR build ----------------
__global__ void k_zero_deg() {
    int i = blockIdx.x * blockDim.x + threadIdx.x;
    if (i < NN) g_deg[i] = 0;
}
__global__ void k_hist(const int* __restrict__ dst) {
    int e = blockIdx.x * blockDim.x + threadIdx.x;
    if (e < EE) atomicAdd(&g_deg[dst[e]], 1);
}
__global__ void k_scan1() {
    __shared__ int sm[SCAN_BS];
    int tid = threadIdx.x;
    int i = blockIdx.x * SCAN_BS + tid;
    int v = (i < NN) ? g_deg[i] : 0;
    sm[tid] = v;
    __syncthreads();
    for (int off = 1; off < SCAN_BS; off <<= 1) {
        int t = (tid >= off) ? sm[tid - off] : 0;
        __syncthreads();
        sm[tid] += t;
        __syncthreads();
    }
    if (i < NN) g_incl[i] = sm[tid];
    if (tid == SCAN_BS - 1) g_bsum[blockIdx.x] = sm[tid];
}
__global__ void k_scan2() {
    if (threadIdx.x == 0) {
        int s = 0;
        for (int b = 0; b < SCAN_NB; b++) { g_boff[b] = s; s += g_bsum[b]; }
    }
}
__global__ void k_scan3() {
    int i = blockIdx.x * blockDim.x + threadIdx.x;
    if (i >= NN) return;
    int rs = g_boff[i >> 10] + g_incl[i] - g_deg[i];
    g_rs[i] = rs;
    g_cur[i] = rs;
}
__global__ void k_scatter(const int* __restrict__ src, const int* __restrict__ dst) {
    int e = blockIdx.x * blockDim.x + threadIdx.x;
    if (e >= EE) return;
    int p = atomicAdd(&g_cur[dst[e]], 1);
    g_csrc[p] = src[e];
}

// ---- aggregation: x = fp16(0.9*sum h[src] + 0.1*h0) ----
// h, h0, x all fp16; accumulation fp32. One uint4 (8 ch) per lane per row.
__global__ void k_agg() {
    int node = blockIdx.x * blockDim.y + threadIdx.y;
    if (node >= NN) return;
    int lane = threadIdx.x;
    int s = g_rs[node], d = g_deg[node];
    float acc[8] = {0.f, 0.f, 0.f, 0.f, 0.f, 0.f, 0.f, 0.f};
    for (int e = 0; e < d; e++) {
        int sn = g_csrc[s + e];
        uint4 v = *(const uint4*)(g_h + (size_t)sn * CH + lane * 8);
        float2 f0 = unpackh2(v.x), f1 = unpackh2(v.y);
        float2 f2 = unpackh2(v.z), f3 = unpackh2(v.w);
        acc[0] += f0.x; acc[1] += f0.y; acc[2] += f1.x; acc[3] += f1.y;
        acc[4] += f2.x; acc[5] += f2.y; acc[6] += f3.x; acc[7] += f3.y;
    }
    uint4 z = *(const uint4*)(g_h0 + (size_t)node * CH + lane * 8);
    float2 z0 = unpackh2(z.x), z1 = unpackh2(z.y);
    float2 z2 = unpackh2(z.z), z3 = unpackh2(z.w);
    float o[8];
    o[0] = 0.9f * acc[0] + 0.1f * z0.x;  o[1] = 0.9f * acc[1] + 0.1f * z0.y;
    o[2] = 0.9f * acc[2] + 0.1f * z1.x;  o[3] = 0.9f * acc[3] + 0.1f * z1.y;
    o[4] = 0.9f * acc[4] + 0.1f * z2.x;  o[5] = 0.9f * acc[5] + 0.1f * z2.y;
    o[6] = 0.9f * acc[6] + 0.1f * z3.x;  o[7] = 0.9f * acc[7] + 0.1f * z3.y;
    uint4 w;
    w.x = packh2(o[0], o[1]);  w.y = packh2(o[2], o[3]);
    w.z = packh2(o[4], o[5]);  w.w = packh2(o[6], o[7]);
    *(uint4*)(g_x + (size_t)node * CH + lane * 8) = w;
}

// ---------------- 2-pass fp16 HMMA GEMM: C = relu(A @ (Bh+Bl)^T (+bias)) ---
// A: single fp16 plane [PADN][256]; B: fp16 hi/lo [Ndim][256].
// CTA tile 128M x 128N; blockIdx.x = n-tile (fast -> A shared via L2),
// blockIdx.y = m-tile. K in 8 chunks of 32, 2-stage cp.async, occ 2.
#define GSTR 80            // smem row stride bytes (32 fp16 + pad)
#define GPLANE 10240       // 128*80
#define GSTAGE 30720       // 3 planes (A, Bh, Bl)
#define GSM_TOTAL 61440    // 2 stages

__global__ void __launch_bounds__(512, 2)
k_gemm2(const __half* __restrict__ A,
        const __half* __restrict__ Bh, const __half* __restrict__ Bl,
        const float* __restrict__ bias,
        __half* __restrict__ C, __half* __restrict__ C2, int ccol0, int M) {
    extern __shared__ __align__(16) char smem[];
    const uint32_t sb = smem_u32(smem);
    const int tid = threadIdx.x;
    const int wid = tid >> 5, lane = tid & 31;
    const int wm = wid >> 2, wn = wid & 3;       // 4x4 warp grid, warp tile 32x32
    const int m0 = blockIdx.y * 128;
    const int n0 = blockIdx.x * 128;

    float acc[2][4][4];
    #pragma unroll
    for (int mt = 0; mt < 2; mt++)
        #pragma unroll
        for (int nt = 0; nt < 4; nt++)
            #pragma unroll
            for (int i = 0; i < 4; i++) acc[mt][nt][i] = 0.f;

    const int lrow = tid >> 2, lseg = tid & 3;   // 128 rows x 4 segs of 16B
    auto load_chunk = [&](int c, int st) {
        const int k0 = c * 32;
        const uint32_t base = sb + st * GSTAGE;
        const uint32_t dst = base + lrow * GSTR + lseg * 16;
        size_t asrc = (size_t)(m0 + lrow) * CH + k0 + lseg * 8;
        size_t bsrc = (size_t)(n0 + lrow) * CH + k0 + lseg * 8;
        CP16(dst,              A  + asrc);
        CP16(dst + GPLANE,     Bh + bsrc);
        CP16(dst + 2 * GPLANE, Bl + bsrc);
        CP_COMMIT();
    };

    load_chunk(0, 0);

    for (int c = 0; c < 8; c++) {
        if (c + 1 < 8) load_chunk(c + 1, (c + 1) & 1);
        if (c + 1 < 8) { CP_WAIT(1); } else { CP_WAIT(0); }
        __syncthreads();

        const uint32_t base = sb + (c & 1) * GSTAGE;
        #pragma unroll
        for (int ks = 0; ks < 2; ks++) {
            const int akoff = ks * 32 + (lane >> 4) * 16;
            uint32_t a[2][4];
            const int arow = wm * 32 + (lane & 15);
            #pragma unroll
            for (int mt = 0; mt < 2; mt++)
                ldsm_x4(a[mt], base + (uint32_t)(arow + mt * 16) * GSTR + akoff);
            #pragma unroll
            for (int ntp = 0; ntp < 2; ntp++) {
                const int brow = wn * 32 + ntp * 16 + (lane & 15);
                uint32_t off = (uint32_t)brow * GSTR + akoff;
                uint32_t bh[4], bl[4];
                ldsm_x4(bh, base + GPLANE + off);
                ldsm_x4(bl, base + 2 * GPLANE + off);
                #pragma unroll
                for (int mt = 0; mt < 2; mt++) {
                    float* a0 = acc[mt][2 * ntp];
                    float* a1 = acc[mt][2 * ntp + 1];
                    mma16816h(a0, a[mt], bh[0], bh[2]);
                    mma16816h(a0, a[mt], bl[0], bl[2]);
                    mma16816h(a1, a[mt], bh[1], bh[3]);
                    mma16816h(a1, a[mt], bl[1], bl[3]);
                }
            }
        }
        __syncthreads();
    }

    // ---- epilogue: bias + relu + fp16 store ----
    #pragma unroll
    for (int mt = 0; mt < 2; mt++) {
        #pragma unroll
        for (int nt = 0; nt < 4; nt++) {
            int colL = wn * 32 + nt * 8 + (lane & 3) * 2;
            float2 bv = make_float2(0.f, 0.f);
            if (bias) bv = *(const float2*)(bias + n0 + colL);
            int colg = ccol0 + n0 + colL;
            #pragma unroll
            for (int half = 0; half < 2; half++) {
                int row = m0 + wm * 32 + mt * 16 + (lane >> 2) + half * 8;
                if (row >= M) continue;
                float vx = fmaxf(acc[mt][nt][half * 2 + 0] + bv.x, 0.f);
                float vy = fmaxf(acc[mt][nt][half * 2 + 1] + bv.y, 0.f);
                uint32_t pv = packh2(vx, vy);
                *(uint32_t*)(C + (size_t)row * CH + colg) = pv;
                if (C2) *(uint32_t*)(C2 + (size_t)row * CH + colg) = pv;
            }
        }
    }
}

// ---------------- final projection: out = h @ out_w + out_b  [N,40] ------
__global__ void __launch_bounds__(256)
k_out(const __half* __restrict__ H, const float* __restrict__ Wo,
      const float* __restrict__ bo, float* __restrict__ O) {
    __shared__ float As[256][33];
    __shared__ float Ws[32][40];
    const int tid = threadIdx.x;
    const int m0 = blockIdx.x * 256;
    const int rg = tid >> 1;
    const int cg = tid & 1;

    float acc[2][20];
    #pragma unroll
    for (int r = 0; r < 2; r++)
        #pragma unroll
        for (int j = 0; j < 20; j++) acc[r][j] = 0.f;

    for (int kt = 0; kt < CH; kt += 32) {
        #pragma unroll
        for (int i = 0; i < 16; i++) {
            int idx = tid + i * 256;            // 0..4095 half2 slots
            int r = idx >> 4, kh = (idx & 15) * 2;
            float2 f = make_float2(0.f, 0.f);
            int row = m0 + r;
            if (row < NN) {
                uint32_t u = *(const uint32_t*)(H + (size_t)row * CH + kt + kh);
                f = unpackh2(u);
            }
            As[r][kh + 0] = f.x;
            As[r][kh + 1] = f.y;
        }
        for (int i = tid; i < 32 * NCLS; i += 256)
            Ws[i / NCLS][i % NCLS] = Wo[(size_t)(kt + i / NCLS) * NCLS + (i % NCLS)];
        __syncthreads();
        #pragma unroll
        for (int k = 0; k < 32; k++) {
            float a0 = As[rg * 2 + 0][k];
            float a1 = As[rg * 2 + 1][k];
            #pragma unroll
            for (int j = 0; j < 20; j++) {
                float w = Ws[k][cg * 20 + j];
                acc[0][j] = fmaf(a0, w, acc[0][j]);
                acc[1][j] = fmaf(a1, w, acc[1][j]);
            }
        }
        __syncthreads();
    }
    #pragma unroll
    for (int rr = 0; rr < 2; rr++) {
        int row = m0 + rg * 2 + rr;
        if (row >= NN) continue;
        #pragma unroll
        for (int j = 0; j < 20; j++) {
            int col = cg * 20 + j;
            O[(size_t)row * NCLS + col] = acc[rr][j] + bo[col];
        }
    }
}

// ---------------- launch ----------------
extern "C" void kernel_launch(void* const* d_in, const int* in_sizes, int n_in,
                              void* d_out, int out_size) {
    const float* x0    = (const float*)d_in[0];
    const float* x1    = (const float*)d_in[1];
    const int*   ei    = (const int*)d_in[2];
    const float* lin_w = (const float*)d_in[3];
    const float* lin_b = (const float*)d_in[4];
    const float* gcn_w = (const float*)d_in[5];
    const float* out_w = (const float*)d_in[6];
    const float* out_b = (const float*)d_in[7];
    float* out = (float*)d_out;

    const int* e_src = ei;
    const int* e_dst = ei + EE;

    __half *p_h0, *p_h, *p_x, *p_a0, *p_a1;
    __half *p_Bh, *p_Bl, *p_BLh, *p_BLl;
    cudaGetSymbolAddress((void**)&p_h0,  g_h0);
    cudaGetSymbolAddress((void**)&p_h,   g_h);
    cudaGetSymbolAddress((void**)&p_x,   g_x);
    cudaGetSymbolAddress((void**)&p_a0,  g_a0);
    cudaGetSymbolAddress((void**)&p_a1,  g_a1);
    cudaGetSymbolAddress((void**)&p_Bh,  g_Bh);
    cudaGetSymbolAddress((void**)&p_Bl,  g_Bl);
    cudaGetSymbolAddress((void**)&p_BLh, g_BLh);
    cudaGetSymbolAddress((void**)&p_BLl, g_BLl);

    cudaFuncSetAttribute(k_gemm2, cudaFuncAttributeMaxDynamicSharedMemorySize, GSM_TOTAL);

    const int mtiles = PADN / 128;   // 782

    // ---- launch order arranged so launch index 3 (profiled) = lin GEMM ----
    k_prep_lin<<<(2 * 128 * 256 + 255) / 256, 256>>>(lin_w);           // 0
    k_split<<<(NN * 32 + 255) / 256, 256>>>(x0, p_a0);                 // 1
    k_split<<<(NN * 32 + 255) / 256, 256>>>(x1, p_a1);                 // 2
    k_gemm2<<<dim3(1, mtiles), 512, GSM_TOTAL>>>(p_a0, p_BLh,         p_BLl,         lin_b,       p_h0, p_h, 0,   NN);  // 3 <- profiled
    k_gemm2<<<dim3(1, mtiles), 512, GSM_TOTAL>>>(p_a1, p_BLh + 32768, p_BLl + 32768, lin_b + 128, p_h0, p_h, 128, NN);  // 4

    k_prep_gcn<<<(LL * 256 * 256 + 255) / 256, 256>>>(gcn_w);          // 5
    k_zero_deg<<<(NN + 255) / 256, 256>>>();
    k_hist<<<(EE + 255) / 256, 256>>>(e_dst);
    k_scan1<<<SCAN_NB, SCAN_BS>>>();
    k_scan2<<<1, 32>>>();
    k_scan3<<<(NN + 255) / 256, 256>>>();
    k_scatter<<<(EE + 255) / 256, 256>>>(e_src, e_dst);

    // 8 GCNII layers
    for (int l = 0; l < LL; l++) {
        k_agg<<<(NN + 7) / 8, dim3(32, 8)>>>();
        k_gemm2<<<dim3(2, mtiles), 512, GSM_TOTAL>>>(p_x,
                                                     p_Bh + (size_t)l * 65536,
                                                     p_Bl + (size_t)l * 65536,
                                                     nullptr, p_h, nullptr, 0, NN);
    }

    // output projection
    k_out<<<(NN + 255) / 256, 256>>>(p_h, out_w, out_b, out);
}

// round 9
// speedup vs baseline: 2.1412x; 1.2375x over previous
#include <cuda_runtime.h>
#include <cuda_fp16.h>
#include <math.h>
#include <stdint.h>

#define NN 100000
#define PADN 100096   // 782 * 128
#define EE 300000
#define CH 256
#define LL 8
#define NCLS 40
#define SCAN_BS 1024
#define SCAN_NB 98   // ceil(100000/1024)

// ---------------- helpers ----------------
__device__ __forceinline__ uint32_t smem_u32(const void* p) {
    uint32_t a;
    asm("{ .reg .u64 t; cvta.to.shared.u64 t, %1; cvt.u32.u64 %0, t; }" : "=r"(a) : "l"(p));
    return a;
}
__device__ __forceinline__ void ldsm_x4(uint32_t* r, uint32_t addr) {
    asm volatile("ldmatrix.sync.aligned.m8n8.x4.shared.b16 {%0,%1,%2,%3}, [%4];"
                 : "=r"(r[0]), "=r"(r[1]), "=r"(r[2]), "=r"(r[3]) : "r"(addr));
}
__device__ __forceinline__ void mma16816h(float* d, const uint32_t* a, uint32_t b0, uint32_t b1) {
    asm volatile(
        "mma.sync.aligned.m16n8k16.row.col.f32.f16.f16.f32 "
        "{%0,%1,%2,%3}, {%4,%5,%6,%7}, {%8,%9}, {%0,%1,%2,%3};"
        : "+f"(d[0]), "+f"(d[1]), "+f"(d[2]), "+f"(d[3])
        : "r"(a[0]), "r"(a[1]), "r"(a[2]), "r"(a[3]), "r"(b0), "r"(b1));
}
#define CP16(dst, src) \
    asm volatile("cp.async.cg.shared.global [%0], [%1], 16;" :: "r"(dst), "l"(src))
#define CP_COMMIT() asm volatile("cp.async.commit_group;" ::: "memory")
#define CP_WAIT(n)  asm volatile("cp.async.wait_group %0;" :: "n"(n) : "memory")

__device__ __forceinline__ uint32_t packh2(float a, float b) {
    __half2 h = __floats2half2_rn(a, b);
    return *(uint32_t*)&h;
}
__device__ __forceinline__ float2 unpackh2(uint32_t u) {
    return __half22float2(*(__half2*)&u);
}

// ---------------- device scratch ----------------
__device__ __half g_h0[(size_t)PADN * CH];          // fp16 h0
__device__ __half g_h [(size_t)PADN * CH];          // fp16 h
__device__ __half g_x [(size_t)PADN * CH];          // fp16 x plane (zero-padded tail)
__device__ __half g_a0[(size_t)PADN * CH];          // fp16 x0
__device__ __half g_a1[(size_t)PADN * CH];          // fp16 x1
__device__ __half g_Bw [(size_t)LL * 256 * 256];    // gcn eff weights [l][n][k], single fp16
__device__ __half g_BLh[(size_t)2 * 128 * 256];     // lin weights [v][n][k] hi
__device__ __half g_BLl[(size_t)2 * 128 * 256];     // lo
__device__ int   g_deg[NN];
__device__ int   g_rs [NN];
__device__ int   g_cur[NN];
__device__ int   g_incl[NN];
__device__ int   g_bsum[SCAN_NB];
__device__ int   g_boff[SCAN_NB];
__device__ int   g_csrc[EE];

// ---------------- weight prep ----------------
__global__ void k_prep_gcn(const float* __restrict__ gcn_w) {
    int idx = blockIdx.x * blockDim.x + threadIdx.x;
    if (idx >= LL * 256 * 256) return;
    int l = idx >> 16;
    int n = (idx >> 8) & 255;
    int k = idx & 255;
    float beta = logf(0.5f / (float)(l + 1) + 1.0f);
    float w = gcn_w[l * 65536 + k * 256 + n];
    float eff = beta * w + ((n == k) ? (1.0f - beta) : 0.0f);
    g_Bw[idx] = __float2half_rn(eff);
}
__global__ void k_prep_lin(const float* __restrict__ lin_w) {
    int idx = blockIdx.x * blockDim.x + threadIdx.x;
    if (idx >= 2 * 128 * 256) return;
    int v = idx >> 15;
    int n = (idx >> 8) & 127;
    int k = idx & 255;
    float w = lin_w[v * 32768 + k * 128 + n];
    __half hi = __float2half_rn(w);
    g_BLh[idx] = hi;
    g_BLl[idx] = __float2half_rn(w - __half2float(hi));
}

// split fp32 input into single fp16 plane
__global__ void k_split(const float* __restrict__ src, __half* __restrict__ dst) {
    int i = blockIdx.x * blockDim.x + threadIdx.x;   // group of 8 elems
    if (i >= NN * 32) return;
    const float4* s = (const float4*)(src + (size_t)i * 8);
    float4 v0 = s[0], v1 = s[1];
    uint4 o;
    o.x = packh2(v0.x, v0.y);  o.y = packh2(v0.z, v0.w);
    o.z = packh2(v1.x, v1.y);  o.w = packh2(v1.z, v1.w);
    *(uint4*)(dst + (size_t)i * 8) = o;
}

// ---------------- CSR build ----------------
__global__ void k_zero_deg() {
    int i = blockIdx.x * blockDim.x + threadIdx.x;
    if (i < NN) g_deg[i] = 0;
}
__global__ void k_hist(const int* __restrict__ dst) {
    int e = blockIdx.x * blockDim.x + threadIdx.x;
    if (e < EE) atomicAdd(&g_deg[dst[e]], 1);
}
__global__ void k_scan1() {
    __shared__ int sm[SCAN_BS];
    int tid = threadIdx.x;
    int i = blockIdx.x * SCAN_BS + tid;
    int v = (i < NN) ? g_deg[i] : 0;
    sm[tid] = v;
    __syncthreads();
    for (int off = 1; off < SCAN_BS; off <<= 1) {
        int t = (tid >= off) ? sm[tid - off] : 0;
        __syncthreads();
        sm[tid] += t;
        __syncthreads();
    }
    if (i < NN) g_incl[i] = sm[tid];
    if (tid == SCAN_BS - 1) g_bsum[blockIdx.x] = sm[tid];
}
__global__ void k_scan2() {
    if (threadIdx.x == 0) {
        int s = 0;
        for (int b = 0; b < SCAN_NB; b++) { g_boff[b] = s; s += g_bsum[b]; }
    }
}
__global__ void k_scan3() {
    int i = blockIdx.x * blockDim.x + threadIdx.x;
    if (i >= NN) return;
    int rs = g_boff[i >> 10] + g_incl[i] - g_deg[i];
    g_rs[i] = rs;
    g_cur[i] = rs;
}
__global__ void k_scatter(const int* __restrict__ src, const int* __restrict__ dst) {
    int e = blockIdx.x * blockDim.x + threadIdx.x;
    if (e >= EE) return;
    int p = atomicAdd(&g_cur[dst[e]], 1);
    g_csrc[p] = src[e];
}

// ---- aggregation: x = fp16(0.9*sum h[src] + 0.1*h0) ----
__global__ void k_agg() {
    int node = blockIdx.x * blockDim.y + threadIdx.y;
    if (node >= NN) return;
    int lane = threadIdx.x;
    int s = g_rs[node], d = g_deg[node];
    float acc[8] = {0.f, 0.f, 0.f, 0.f, 0.f, 0.f, 0.f, 0.f};
    for (int e = 0; e < d; e++) {
        int sn = g_csrc[s + e];
        uint4 v = *(const uint4*)(g_h + (size_t)sn * CH + lane * 8);
        float2 f0 = unpackh2(v.x), f1 = unpackh2(v.y);
        float2 f2 = unpackh2(v.z), f3 = unpackh2(v.w);
        acc[0] += f0.x; acc[1] += f0.y; acc[2] += f1.x; acc[3] += f1.y;
        acc[4] += f2.x; acc[5] += f2.y; acc[6] += f3.x; acc[7] += f3.y;
    }
    uint4 z = *(const uint4*)(g_h0 + (size_t)node * CH + lane * 8);
    float2 z0 = unpackh2(z.x), z1 = unpackh2(z.y);
    float2 z2 = unpackh2(z.z), z3 = unpackh2(z.w);
    float o[8];
    o[0] = 0.9f * acc[0] + 0.1f * z0.x;  o[1] = 0.9f * acc[1] + 0.1f * z0.y;
    o[2] = 0.9f * acc[2] + 0.1f * z1.x;  o[3] = 0.9f * acc[3] + 0.1f * z1.y;
    o[4] = 0.9f * acc[4] + 0.1f * z2.x;  o[5] = 0.9f * acc[5] + 0.1f * z2.y;
    o[6] = 0.9f * acc[6] + 0.1f * z3.x;  o[7] = 0.9f * acc[7] + 0.1f * z3.y;
    uint4 w;
    w.x = packh2(o[0], o[1]);  w.y = packh2(o[2], o[3]);
    w.z = packh2(o[4], o[5]);  w.w = packh2(o[6], o[7]);
    *(uint4*)(g_x + (size_t)node * CH + lane * 8) = w;
}

// ---------------- 2-pass fp16 HMMA GEMM (lin): C = relu(A @ (Bh+Bl)^T + bias)
#define GSTR 80            // smem row stride bytes (32 fp16 + pad)
#define GPLANE 10240       // 128*80
#define GSTAGE 30720       // 3 planes (A, Bh, Bl)
#define GSM_TOTAL 61440    // 2 stages

__global__ void __launch_bounds__(512, 2)
k_gemm2(const __half* __restrict__ A,
        const __half* __restrict__ Bh, const __half* __restrict__ Bl,
        const float* __restrict__ bias,
        __half* __restrict__ C, __half* __restrict__ C2, int ccol0, int M) {
    extern __shared__ __align__(16) char smem[];
    const uint32_t sb = smem_u32(smem);
    const int tid = threadIdx.x;
    const int wid = tid >> 5, lane = tid & 31;
    const int wm = wid >> 2, wn = wid & 3;
    const int m0 = blockIdx.y * 128;
    const int n0 = blockIdx.x * 128;

    float acc[2][4][4];
    #pragma unroll
    for (int mt = 0; mt < 2; mt++)
        #pragma unroll
        for (int nt = 0; nt < 4; nt++)
            #pragma unroll
            for (int i = 0; i < 4; i++) acc[mt][nt][i] = 0.f;

    const int lrow = tid >> 2, lseg = tid & 3;
    auto load_chunk = [&](int c, int st) {
        const int k0 = c * 32;
        const uint32_t base = sb + st * GSTAGE;
        const uint32_t dst = base + lrow * GSTR + lseg * 16;
        size_t asrc = (size_t)(m0 + lrow) * CH + k0 + lseg * 8;
        size_t bsrc = (size_t)(n0 + lrow) * CH + k0 + lseg * 8;
        CP16(dst,              A  + asrc);
        CP16(dst + GPLANE,     Bh + bsrc);
        CP16(dst + 2 * GPLANE, Bl + bsrc);
        CP_COMMIT();
    };

    load_chunk(0, 0);

    for (int c = 0; c < 8; c++) {
        if (c + 1 < 8) load_chunk(c + 1, (c + 1) & 1);
        if (c + 1 < 8) { CP_WAIT(1); } else { CP_WAIT(0); }
        __syncthreads();

        const uint32_t base = sb + (c & 1) * GSTAGE;
        #pragma unroll
        for (int ks = 0; ks < 2; ks++) {
            const int akoff = ks * 32 + (lane >> 4) * 16;
            uint32_t a[2][4];
            const int arow = wm * 32 + (lane & 15);
            #pragma unroll
            for (int mt = 0; mt < 2; mt++)
                ldsm_x4(a[mt], base + (uint32_t)(arow + mt * 16) * GSTR + akoff);
            #pragma unroll
            for (int ntp = 0; ntp < 2; ntp++) {
                const int brow = wn * 32 + ntp * 16 + (lane & 15);
                uint32_t off = (uint32_t)brow * GSTR + akoff;
                uint32_t bh[4], bl[4];
                ldsm_x4(bh, base + GPLANE + off);
                ldsm_x4(bl, base + 2 * GPLANE + off);
                #pragma unroll
                for (int mt = 0; mt < 2; mt++) {
                    float* a0 = acc[mt][2 * ntp];
                    float* a1 = acc[mt][2 * ntp + 1];
                    mma16816h(a0, a[mt], bh[0], bh[2]);
                    mma16816h(a0, a[mt], bl[0], bl[2]);
                    mma16816h(a1, a[mt], bh[1], bh[3]);
                    mma16816h(a1, a[mt], bl[1], bl[3]);
                }
            }
        }
        __syncthreads();
    }

    #pragma unroll
    for (int mt = 0; mt < 2; mt++) {
        #pragma unroll
        for (int nt = 0; nt < 4; nt++) {
            int colL = wn * 32 + nt * 8 + (lane & 3) * 2;
            float2 bv = make_float2(0.f, 0.f);
            if (bias) bv = *(const float2*)(bias + n0 + colL);
            int colg = ccol0 + n0 + colL;
            #pragma unroll
            for (int half = 0; half < 2; half++) {
                int row = m0 + wm * 32 + mt * 16 + (lane >> 2) + half * 8;
                if (row >= M) continue;
                float vx = fmaxf(acc[mt][nt][half * 2 + 0] + bv.x, 0.f);
                float vy = fmaxf(acc[mt][nt][half * 2 + 1] + bv.y, 0.f);
                uint32_t pv = packh2(vx, vy);
                *(uint32_t*)(C + (size_t)row * CH + colg) = pv;
                if (C2) *(uint32_t*)(C2 + (size_t)row * CH + colg) = pv;
            }
        }
    }
}

// ---------------- 1-pass fp16 HMMA GEMM (layers): C = relu(A @ Bw^T) -------
#define G1STAGE 20480      // 2 planes (A, B)
#define G1SM_TOTAL 40960   // 2 stages

__global__ void __launch_bounds__(512, 2)
k_gemm1(const __half* __restrict__ A, const __half* __restrict__ Bw,
        __half* __restrict__ C, int M) {
    extern __shared__ __align__(16) char smem[];
    const uint32_t sb = smem_u32(smem);
    const int tid = threadIdx.x;
    const int wid = tid >> 5, lane = tid & 31;
    const int wm = wid >> 2, wn = wid & 3;
    const int m0 = blockIdx.y * 128;
    const int n0 = blockIdx.x * 128;

    float acc[2][4][4];
    #pragma unroll
    for (int mt = 0; mt < 2; mt++)
        #pragma unroll
        for (int nt = 0; nt < 4; nt++)
            #pragma unroll
            for (int i = 0; i < 4; i++) acc[mt][nt][i] = 0.f;

    const int lrow = tid >> 2, lseg = tid & 3;
    auto load_chunk = [&](int c, int st) {
        const int k0 = c * 32;
        const uint32_t base = sb + st * G1STAGE;
        const uint32_t dst = base + lrow * GSTR + lseg * 16;
        size_t asrc = (size_t)(m0 + lrow) * CH + k0 + lseg * 8;
        size_t bsrc = (size_t)(n0 + lrow) * CH + k0 + lseg * 8;
        CP16(dst,          A  + asrc);
        CP16(dst + GPLANE, Bw + bsrc);
        CP_COMMIT();
    };

    load_chunk(0, 0);

    for (int c = 0; c < 8; c++) {
        if (c + 1 < 8) load_chunk(c + 1, (c + 1) & 1);
        if (c + 1 < 8) { CP_WAIT(1); } else { CP_WAIT(0); }
        __syncthreads();

        const uint32_t base = sb + (c & 1) * G1STAGE;
        #pragma unroll
        for (int ks = 0; ks < 2; ks++) {
            const int akoff = ks * 32 + (lane >> 4) * 16;
            uint32_t a[2][4];
            const int arow = wm * 32 + (lane & 15);
            #pragma unroll
            for (int mt = 0; mt < 2; mt++)
                ldsm_x4(a[mt], base + (uint32_t)(arow + mt * 16) * GSTR + akoff);
            #pragma unroll
            for (int ntp = 0; ntp < 2; ntp++) {
                const int brow = wn * 32 + ntp * 16 + (lane & 15);
                uint32_t bw[4];
                ldsm_x4(bw, base + GPLANE + (uint32_t)brow * GSTR + akoff);
                #pragma unroll
                for (int mt = 0; mt < 2; mt++) {
                    mma16816h(acc[mt][2 * ntp],     a[mt], bw[0], bw[2]);
                    mma16816h(acc[mt][2 * ntp + 1], a[mt], bw[1], bw[3]);
                }
            }
        }
        __syncthreads();
    }

    #pragma unroll
    for (int mt = 0; mt < 2; mt++) {
        #pragma unroll
        for (int nt = 0; nt < 4; nt++) {
            int colg = n0 + wn * 32 + nt * 8 + (lane & 3) * 2;
            #pragma unroll
            for (int half = 0; half < 2; half++) {
                int row = m0 + wm * 32 + mt * 16 + (lane >> 2) + half * 8;
                if (row >= M) continue;
                float vx = fmaxf(acc[mt][nt][half * 2 + 0], 0.f);
                float vy = fmaxf(acc[mt][nt][half * 2 + 1], 0.f);
                *(uint32_t*)(C + (size_t)row * CH + colg) = packh2(vx, vy);
            }
        }
    }
}

// ---------------- final projection: out = h @ out_w + out_b  [N,40] ------
__global__ void __launch_bounds__(256)
k_out(const __half* __restrict__ H, const float* __restrict__ Wo,
      const float* __restrict__ bo, float* __restrict__ O) {
    __shared__ float As[256][33];
    __shared__ float Ws[32][40];
    const int tid = threadIdx.x;
    const int m0 = blockIdx.x * 256;
    const int rg = tid >> 1;
    const int cg = tid & 1;

    float acc[2][20];
    #pragma unroll
    for (int r = 0; r < 2; r++)
        #pragma unroll
        for (int j = 0; j < 20; j++) acc[r][j] = 0.f;

    for (int kt = 0; kt < CH; kt += 32) {
        #pragma unroll
        for (int i = 0; i < 16; i++) {
            int idx = tid + i * 256;
            int r = idx >> 4, kh = (idx & 15) * 2;
            float2 f = make_float2(0.f, 0.f);
            int row = m0 + r;
            if (row < NN) {
                uint32_t u = *(const uint32_t*)(H + (size_t)row * CH + kt + kh);
                f = unpackh2(u);
            }
            As[r][kh + 0] = f.x;
            As[r][kh + 1] = f.y;
        }
        for (int i = tid; i < 32 * NCLS; i += 256)
            Ws[i / NCLS][i % NCLS] = Wo[(size_t)(kt + i / NCLS) * NCLS + (i % NCLS)];
        __syncthreads();
        #pragma unroll
        for (int k = 0; k < 32; k++) {
            float a0 = As[rg * 2 + 0][k];
            float a1 = As[rg * 2 + 1][k];
            #pragma unroll
            for (int j = 0; j < 20; j++) {
                float w = Ws[k][cg * 20 + j];
                acc[0][j] = fmaf(a0, w, acc[0][j]);
                acc[1][j] = fmaf(a1, w, acc[1][j]);
            }
        }
        __syncthreads();
    }
    #pragma unroll
    for (int rr = 0; rr < 2; rr++) {
        int row = m0 + rg * 2 + rr;
        if (row >= NN) continue;
        #pragma unroll
        for (int j = 0; j < 20; j++) {
            int col = cg * 20 + j;
            O[(size_t)row * NCLS + col] = acc[rr][j] + bo[col];
        }
    }
}

// ---------------- launch ----------------
extern "C" void kernel_launch(void* const* d_in, const int* in_sizes, int n_in,
                              void* d_out, int out_size) {
    const float* x0    = (const float*)d_in[0];
    const float* x1    = (const float*)d_in[1];
    const int*   ei    = (const int*)d_in[2];
    const float* lin_w = (const float*)d_in[3];
    const float* lin_b = (const float*)d_in[4];
    const float* gcn_w = (const float*)d_in[5];
    const float* out_w = (const float*)d_in[6];
    const float* out_b = (const float*)d_in[7];
    float* out = (float*)d_out;

    const int* e_src = ei;
    const int* e_dst = ei + EE;

    __half *p_h0, *p_h, *p_x, *p_a0, *p_a1;
    __half *p_Bw, *p_BLh, *p_BLl;
    cudaGetSymbolAddress((void**)&p_h0,  g_h0);
    cudaGetSymbolAddress((void**)&p_h,   g_h);
    cudaGetSymbolAddress((void**)&p_x,   g_x);
    cudaGetSymbolAddress((void**)&p_a0,  g_a0);
    cudaGetSymbolAddress((void**)&p_a1,  g_a1);
    cudaGetSymbolAddress((void**)&p_Bw,  g_Bw);
    cudaGetSymbolAddress((void**)&p_BLh, g_BLh);
    cudaGetSymbolAddress((void**)&p_BLl, g_BLl);

    cudaFuncSetAttribute(k_gemm2, cudaFuncAttributeMaxDynamicSharedMemorySize, GSM_TOTAL);
    cudaFuncSetAttribute(k_gemm1, cudaFuncAttributeMaxDynamicSharedMemorySize, G1SM_TOTAL);

    const int mtiles = PADN / 128;   // 782

    // ---- launch order: index 3 (profiled) = lin GEMM ----
    k_prep_lin<<<(2 * 128 * 256 + 255) / 256, 256>>>(lin_w);           // 0
    k_split<<<(NN * 32 + 255) / 256, 256>>>(x0, p_a0);                 // 1
    k_split<<<(NN * 32 + 255) / 256, 256>>>(x1, p_a1);                 // 2
    k_gemm2<<<dim3(1, mtiles), 512, GSM_TOTAL>>>(p_a0, p_BLh,         p_BLl,         lin_b,       p_h0, p_h, 0,   NN);  // 3 <- profiled
    k_gemm2<<<dim3(1, mtiles), 512, GSM_TOTAL>>>(p_a1, p_BLh + 32768, p_BLl + 32768, lin_b + 128, p_h0, p_h, 128, NN);  // 4

    k_prep_gcn<<<(LL * 256 * 256 + 255) / 256, 256>>>(gcn_w);          // 5
    k_zero_deg<<<(NN + 255) / 256, 256>>>();
    k_hist<<<(EE + 255) / 256, 256>>>(e_dst);
    k_scan1<<<SCAN_NB, SCAN_BS>>>();
    k_scan2<<<1, 32>>>();
    k_scan3<<<(NN + 255) / 256, 256>>>();
    k_scatter<<<(EE + 255) / 256, 256>>>(e_src, e_dst);

    // 8 GCNII layers: agg + single-pass GEMM
    for (int l = 0; l < LL; l++) {
        k_agg<<<(NN + 7) / 8, dim3(32, 8)>>>();
        k_gemm1<<<dim3(2, mtiles), 512, G1SM_TOTAL>>>(p_x,
                                                      p_Bw + (size_t)l * 65536,
                                                      p_h, NN);
    }

    // output projection
    k_out<<<(NN + 255) / 256, 256>>>(p_h, out_w, out_b, out);
}